// round 4
// baseline (speedup 1.0000x reference)
#include <cuda_runtime.h>
#include <cuda_fp16.h>
#include <cstdint>

typedef uint32_t u32;

#define SQRTD_F 11.313708498984761f
#define PAD 132

// shared memory byte offsets
#define SM_PI   0                    // Pi  [128][132] f32 (fwd B: row n, col k)
#define SM_PT   67584                // PiT [128][132] f32 (bwd B: row i, col j)
#define SM_A    135168               // A   [128][132] f32
#define SM_MISC 202752
#define SMEM_BYTES 204928

static __device__ __forceinline__ float tf32_rna(float f) {
    u32 u;
    asm("cvt.rna.tf32.f32 %0, %1;" : "=r"(u) : "f"(f));
    return __uint_as_float(u);
}
static __device__ __forceinline__ u32 fb(float f) { return __float_as_uint(f); }

static __device__ __forceinline__ void mma8(float c[4], u32 a0, u32 a1, u32 a2, u32 a3,
                                            u32 b0, u32 b1) {
    asm volatile(
        "mma.sync.aligned.m16n8k8.row.col.f32.tf32.tf32.f32 "
        "{%0,%1,%2,%3},{%4,%5,%6,%7},{%8,%9},{%0,%1,%2,%3};"
        : "+f"(c[0]), "+f"(c[1]), "+f"(c[2]), "+f"(c[3])
        : "r"(a0), "r"(a1), "r"(a2), "r"(a3), "r"(b0), "r"(b1));
}

// One K=128 GEMM over a 32(M) x 64(N) warp tile.
// A, B held fp32 in smem; hi/lo tf32 split done in registers.
// NPROD=4: hh+hl+lh+ll (fp32-exact forward); NPROD=3: hh+hl+lh (backward).
template<int NPROD>
static __device__ __forceinline__ void chain(const float* __restrict__ sA,
                                             const float* __restrict__ sB,
                                             float acc[2][8][4],
                                             int g, int t, int mbase, int nbase) {
    #pragma unroll 1
    for (int ks = 0; ks < 16; ks++) {
        const int k0 = ks * 8;
        u32 bh[8][2], bl[8][2];
        #pragma unroll
        for (int nt = 0; nt < 8; nt++) {
            const float* bp = sB + (nbase + nt * 8 + g) * PAD + k0 + t;
            float b0 = bp[0], b1 = bp[4];
            float h0 = tf32_rna(b0), h1 = tf32_rna(b1);
            bh[nt][0] = fb(h0);
            bh[nt][1] = fb(h1);
            bl[nt][0] = fb(tf32_rna(b0 - h0));
            bl[nt][1] = fb(tf32_rna(b1 - h1));
        }
        u32 ah[2][4], al[2][4];
        #pragma unroll
        for (int mt = 0; mt < 2; mt++) {
            const float* ap = sA + (mbase + mt * 16 + g) * PAD + k0 + t;
            float a0 = ap[0], a1 = ap[8 * PAD], a2 = ap[4], a3 = ap[8 * PAD + 4];
            float h0 = tf32_rna(a0), h1 = tf32_rna(a1);
            float h2 = tf32_rna(a2), h3 = tf32_rna(a3);
            ah[mt][0] = fb(h0); ah[mt][1] = fb(h1); ah[mt][2] = fb(h2); ah[mt][3] = fb(h3);
            al[mt][0] = fb(tf32_rna(a0 - h0));
            al[mt][1] = fb(tf32_rna(a1 - h1));
            al[mt][2] = fb(tf32_rna(a2 - h2));
            al[mt][3] = fb(tf32_rna(a3 - h3));
        }
        // product-major ordering: dependent MMAs on the same acc are 16 apart
        #pragma unroll
        for (int mt = 0; mt < 2; mt++)
            #pragma unroll
            for (int nt = 0; nt < 8; nt++)
                mma8(acc[mt][nt], ah[mt][0], ah[mt][1], ah[mt][2], ah[mt][3],
                     bh[nt][0], bh[nt][1]);
        #pragma unroll
        for (int mt = 0; mt < 2; mt++)
            #pragma unroll
            for (int nt = 0; nt < 8; nt++)
                mma8(acc[mt][nt], ah[mt][0], ah[mt][1], ah[mt][2], ah[mt][3],
                     bl[nt][0], bl[nt][1]);
        #pragma unroll
        for (int mt = 0; mt < 2; mt++)
            #pragma unroll
            for (int nt = 0; nt < 8; nt++)
                mma8(acc[mt][nt], al[mt][0], al[mt][1], al[mt][2], al[mt][3],
                     bh[nt][0], bh[nt][1]);
        if (NPROD == 4) {
            #pragma unroll
            for (int mt = 0; mt < 2; mt++)
                #pragma unroll
                for (int nt = 0; nt < 8; nt++)
                    mma8(acc[mt][nt], al[mt][0], al[mt][1], al[mt][2], al[mt][3],
                         bl[nt][0], bl[nt][1]);
        }
    }
}

__global__ __launch_bounds__(256, 1)
void tq_fused(const float* __restrict__ x, const float* __restrict__ Pi,
              const float* __restrict__ cbk, float* __restrict__ out) {
    extern __shared__ char sm[];
    float* sPi = (float*)(sm + SM_PI);
    float* sPT = (float*)(sm + SM_PT);
    float* sA  = (float*)(sm + SM_A);
    float* s_csd  = (float*)(sm + SM_MISC);          // 16 f32
    float* s_mid  = (float*)(sm + SM_MISC + 64);     // 15 f32
    float* s_part = (float*)(sm + SM_MISC + 128);    // 256 f32
    float* s_cn   = (float*)(sm + SM_MISC + 1152);   // 128 f32
    float* s_nh   = (float*)(sm + SM_MISC + 1664);   // 128 f32

    const int tid = threadIdx.x;
    const int wid = tid >> 5, lane = tid & 31;
    const int g = lane >> 2, t = lane & 3;
    const int mbase = (wid >> 1) * 32;      // 4 M-warp groups
    const int nbase = (wid & 1) * 64;       // 2 N-warp groups
    const int tok0 = blockIdx.x << 7;

    // ---- stage Pi (row-major) and PiT (transposed), both fp32 padded ----
    {
        const int prow = tid >> 1, pcol = (tid & 1) * 64;
        const float4* pr = (const float4*)(Pi + prow * 128 + pcol);
        #pragma unroll
        for (int e = 0; e < 16; e++) {
            float4 p = pr[e];
            *(float4*)(sPi + prow * PAD + pcol + 4 * e) = p;
            sPT[(pcol + 4 * e + 0) * PAD + prow] = p.x;
            sPT[(pcol + 4 * e + 1) * PAD + prow] = p.y;
            sPT[(pcol + 4 * e + 2) * PAD + prow] = p.z;
            sPT[(pcol + 4 * e + 3) * PAD + prow] = p.w;
        }
    }

    // ---- load x (2 threads/token), sum of squares, tables ----
    const int token = tid >> 1, c0h = (tid & 1) * 64;
    const float4* xr = (const float4*)(x + (size_t)(tok0 + token) * 128 + c0h);
    {
        float v[64];
        float ss = 0.f;
        #pragma unroll
        for (int e = 0; e < 16; e++) {
            float4 p = xr[e];
            v[4 * e] = p.x; v[4 * e + 1] = p.y; v[4 * e + 2] = p.z; v[4 * e + 3] = p.w;
            ss += p.x * p.x + p.y * p.y + p.z * p.z + p.w * p.w;
        }
        s_part[tid] = ss;
        if (tid < 16) {
            float c = cbk[tid];
            s_csd[tid] = __fdiv_rn(c, SQRTD_F);
            if (tid < 15) s_mid[tid] = (c + cbk[tid + 1]) * 0.5f;
        }
        __syncthreads();
        if (tid < 128) {
            float s = s_part[2 * tid] + s_part[2 * tid + 1];
            float n = __fsqrt_rn(s);
            s_cn[tid] = fmaxf(n, 1e-8f);
            s_nh[tid] = __half2float(__float2half_rn(n));
        }
        __syncthreads();
        // stage A = x_unit (element-wise IEEE division, matching reference)
        const float c = s_cn[token];
        #pragma unroll
        for (int e = 0; e < 16; e++) {
            *(float4*)(sA + token * PAD + c0h + 4 * e) = make_float4(
                __fdiv_rn(v[4 * e], c),     __fdiv_rn(v[4 * e + 1], c),
                __fdiv_rn(v[4 * e + 2], c), __fdiv_rn(v[4 * e + 3], c));
        }
    }
    __syncthreads();

    float acc[2][8][4];
    #pragma unroll
    for (int i = 0; i < 2; i++)
        #pragma unroll
        for (int j = 0; j < 8; j++)
            #pragma unroll
            for (int k = 0; k < 4; k++) acc[i][j][k] = 0.f;

    // ---- forward: y_raw = x_unit @ Pi^T (fp32-exact via 4-product DF32) ----
    chain<4>(sA, sPi, acc, g, t, mbase, nbase);
    __syncthreads();   // all warps done reading sA

    // ---- quantize: y = y_raw*sqrt_d, argmin via midpoints; write csd fp32 to sA ----
    {
        float mids[15];
        #pragma unroll
        for (int l = 0; l < 15; l++) mids[l] = s_mid[l];
        #pragma unroll
        for (int mt = 0; mt < 2; mt++) {
            #pragma unroll
            for (int nt = 0; nt < 8; nt++) {
                #pragma unroll
                for (int r = 0; r < 4; r++) {
                    float y = acc[mt][nt][r] * SQRTD_F;
                    int idx = 0;
                    #pragma unroll
                    for (int l = 0; l < 15; l++) idx += (y > mids[l]);
                    int row = mbase + mt * 16 + g + (r >> 1) * 8;
                    int col = nbase + nt * 8 + 2 * t + (r & 1);
                    sA[row * PAD + col] = s_csd[idx];
                    acc[mt][nt][r] = 0.f;
                }
            }
        }
    }
    __syncthreads();

    // ---- backward: z = a_hat @ Pi (3-product DF32) ----
    chain<3>(sA, sPT, acc, g, t, mbase, nbase);

    // ---- epilogue: scale by fp16-roundtripped norm, store float2 ----
    #pragma unroll
    for (int mt = 0; mt < 2; mt++) {
        #pragma unroll
        for (int nt = 0; nt < 8; nt++) {
            int row0 = mbase + mt * 16 + g;
            int col  = nbase + nt * 8 + 2 * t;
            float nh0 = s_nh[row0];
            float nh1 = s_nh[row0 + 8];
            *(float2*)(out + (size_t)(tok0 + row0) * 128 + col) =
                make_float2(acc[mt][nt][0] * nh0, acc[mt][nt][1] * nh0);
            *(float2*)(out + (size_t)(tok0 + row0 + 8) * 128 + col) =
                make_float2(acc[mt][nt][2] * nh1, acc[mt][nt][3] * nh1);
        }
    }
}

extern "C" void kernel_launch(void* const* d_in, const int* in_sizes, int n_in,
                              void* d_out, int out_size) {
    const float* x   = (const float*)d_in[0];
    const float* Pi  = (const float*)d_in[1];
    const float* cbk = (const float*)d_in[2];
    float* out = (float*)d_out;

    int ntok = in_sizes[0] / 128;
    int blocks = ntok / 128;

    cudaFuncSetAttribute(tq_fused, cudaFuncAttributeMaxDynamicSharedMemorySize, SMEM_BYTES);
    tq_fused<<<blocks, 256, SMEM_BYTES>>>(x, Pi, cbk, out);
}